// round 10
// baseline (speedup 1.0000x reference)
#include <cuda_runtime.h>
#include <math.h>

#define EPSF 1e-6f
#define TPB 128

__device__ float g_part[8192];
__device__ unsigned int g_ticket;   // zero-init; self-resets each launch

__global__ __launch_bounds__(TPB)
void rotated_iou_loss_kernel(const float* __restrict__ pred,
                             const float* __restrict__ target,
                             const float* __restrict__ weight,
                             float* __restrict__ out,
                             int n, float inv_n)
{
    // One pool, two lives: staging (10*TPB floats) then clip buffers
    // (float2 [slot][tid], 6 + 8 slots). Conflict-free in both lives.
    __shared__ __align__(16) char pool[14 * TPB * sizeof(float2)];
    float* sIn = (float*)pool;

    int tid = threadIdx.x;
    int i = blockIdx.x * TPB + tid;

    {   // coalesced staging
        int base = blockIdx.x * TPB * 5;
        int n5 = 5 * n;
        #pragma unroll
        for (int c = 0; c < 5; c++) {
            int k = tid + c * TPB;
            int g = base + k;
            bool ok = g < n5;
            sIn[k]           = ok ? pred[g]   : 0.0f;
            sIn[5 * TPB + k] = ok ? target[g] : 0.0f;
        }
    }
    __syncthreads();

    int r5 = tid * 5;   // stride-5 smem reads: gcd(5,32)=1 -> conflict-free
    float p_x = sIn[r5+0], p_y = sIn[r5+1], p_w = sIn[r5+2],
          p_h = sIn[r5+3], p_a = sIn[r5+4];
    float t_x = sIn[5*TPB+r5+0], t_y = sIn[5*TPB+r5+1], t_w = sIn[5*TPB+r5+2],
          t_h = sIn[5*TPB+r5+3], t_a = sIn[5*TPB+r5+4];
    __syncthreads();   // staging dead -> pool becomes clip buffers

    float2* pB = (float2*)pool + tid;              // x-slab output, <=6 slots
    float2* pC = (float2*)pool + 6 * TPB + tid;    // y-slab output, <=8 slots

    float loss = 0.0f;
    if (i < n) {
        float tc, ts, cd, sd;
        __sincosf(t_a, &ts, &tc);
        __sincosf(p_a - t_a, &sd, &cd);

        float rx = p_x - t_x, ry = p_y - t_y;
        float cu =  rx * tc + ry * ts;
        float cv = -rx * ts + ry * tc;

        // Pred quad (CCW, reference corner order) in target frame.
        const float dxs[4] = { 0.5f, -0.5f, -0.5f,  0.5f };
        const float dys[4] = { 0.5f,  0.5f, -0.5f, -0.5f };
        float qx[4], qy[4];
        #pragma unroll
        for (int j = 0; j < 4; j++) {
            float lx = p_w * dxs[j], ly = p_h * dys[j];
            qx[j] = cu + lx * cd - ly * sd;
            qy[j] = cv + lx * sd + ly * cd;
        }

        float hw = t_w * 0.5f, hh = t_h * 0.5f;

        // ---- Stage 1: x-slab |x| <= hw (registers -> pB) ----
        float2* curB = pB;
        #pragma unroll
        for (int j = 0; j < 4; j++) {
            float px = qx[j],         py = qy[j];
            float cx = qx[(j+1) & 3], cy = qy[(j+1) & 3];
            bool pL = px < -hw, pH = px > hw;
            bool cL = cx < -hw, cH = cx > hw;
            float dx = cx - px, dy = cy - py;
            float inv = __fdividef(1.0f, dx);
            bool crossL = (pL != cL), crossH = (pH != cH);
            bool firstIsL = dx > 0.0f;
            #pragma unroll
            for (int e = 0; e < 2; e++) {
                bool doL = (e == 0) ? firstIsL : !firstIsL;
                bool cr  = doL ? crossL : crossH;
                if (cr) {
                    float bnd = doL ? -hw : hw;
                    float t = (bnd - px) * inv;
                    *curB = make_float2(bnd, fmaf(t, dy, py));
                    curB += TPB;
                }
            }
            if (!cL && !cH) { *curB = make_float2(cx, cy); curB += TPB; }
        }
        int m1 = (int)((curB - pB) >> 7);   // /TPB

        // ---- Stage 2: y-slab |y| <= hh (pB -> pC), fused sums ----
        // Centroid terms cancel in the cyclic shoelace, so S accumulates on
        // raw coords at emission time (values already in registers).
        float sx = 0.0f, sy = 0.0f, S = 0.0f;
        float fex = 0.0f, fey = 0.0f, prx = 0.0f, pry = 0.0f;
        float2* curC = pC;

        #define EMIT(ex_, ey_) do {                                  \
            float _ex = (ex_), _ey = (ey_);                          \
            if (curC == pC) { fex = _ex; fey = _ey; }                \
            else            { S += prx * _ey - pry * _ex; }          \
            *curC = make_float2(_ex, _ey); curC += TPB;              \
            sx += _ex; sy += _ey;                                    \
            prx = _ex; pry = _ey;                                    \
        } while (0)

        if (m1 > 0) {
            float2 prev = *(curB - TPB);
            float px = prev.x, py = prev.y;
            bool pLo = py < -hh, pHi = py > hh;
            float2* rB = pB;
            for (int j = 0; j < m1; j++, rB += TPB) {
                float2 cur = *rB;
                float cx = cur.x, cy = cur.y;
                bool cLo = cy < -hh, cHi = cy > hh;
                float dx = cx - px, dy = cy - py;
                float inv = __fdividef(1.0f, dy);
                bool crossL = (pLo != cLo), crossH = (pHi != cHi);
                bool firstIsL = dy > 0.0f;
                #pragma unroll
                for (int e = 0; e < 2; e++) {
                    bool doL = (e == 0) ? firstIsL : !firstIsL;
                    bool cr  = doL ? crossL : crossH;
                    if (cr) {
                        float bnd = doL ? -hh : hh;
                        float t = (bnd - py) * inv;
                        EMIT(fmaf(t, dx, px), bnd);
                    }
                }
                if (!cLo && !cHi) EMIT(cx, cy);
                px = cx; py = cy; pLo = cLo; pHi = cHi;
            }
        }
        #undef EMIT
        int m2 = (int)((curC - pC) >> 7);
        if (m2 > 0) S += prx * fey - pry * fex;   // close the cycle

        // ---- Quirky correction: drop the branch-cut edge ----
        // Reference drops cross(p_maxang, p_minang); for a convex CCW polygon
        // that is the unique cyclically-adjacent pair whose centroid-relative
        // ORIGINAL-frame y flips >=0 -> <0 (atan2 wrap at +-pi).
        float inter = 0.0f;
        if (m2 >= 3) {
            float invc = __fdividef(1.0f, (float)m2);
            float mx = sx * invc, my = sy * invc;
            float wcy = mx * ts + my * tc;   // centroid's original-frame y

            float ax = mx, ay = my, bx = mx, by = my;  // default -> corr = 0
            float2 v0 = *pC;
            float wy0 = v0.x * ts + v0.y * tc;
            float ppx = v0.x, ppy = v0.y, wyp = wy0;
            float2* rC = pC + TPB;
            for (int j = 1; j < m2; j++, rC += TPB) {
                float2 v = *rC;
                float wy = v.x * ts + v.y * tc;
                if (wyp >= wcy && wy < wcy) { ax = ppx; ay = ppy; bx = v.x; by = v.y; }
                ppx = v.x; ppy = v.y; wyp = wy;
            }
            if (wyp >= wcy && wy0 < wcy) { ax = ppx; ay = ppy; bx = v0.x; by = v0.y; }

            float qax = ax - mx, qay = ay - my;
            float qbx = bx - mx, qby = by - my;
            float quirky = S - (qax * qby - qay * qbx);
            inter = 0.5f * fabsf(quirky);
        }

        float uni = p_w * p_h + t_w * t_h - inter;
        float iou = __fdividef(inter, fmaxf(uni, EPSF));
        iou = fmaxf(iou, EPSF);
        loss = (1.0f - iou * iou * iou) * weight[i];
    }

    // ---- block reduction -> per-block partial (deterministic) ----
    #pragma unroll
    for (int o = 16; o > 0; o >>= 1)
        loss += __shfl_down_sync(0xffffffffu, loss, o);

    __shared__ float warp_sums[4];
    __shared__ int is_last;
    int lane = tid & 31;
    int wid  = tid >> 5;
    if (lane == 0) warp_sums[wid] = loss;
    __syncthreads();

    if (wid == 0) {
        float v = (lane < 4) ? warp_sums[lane] : 0.0f;
        v += __shfl_down_sync(0xffffffffu, v, 2);
        v += __shfl_down_sync(0xffffffffu, v, 1);
        if (lane == 0) {
            g_part[blockIdx.x] = v;
            __threadfence();
            unsigned int t = atomicAdd(&g_ticket, 1u);
            is_last = (t == gridDim.x - 1) ? 1 : 0;
        }
    }
    __syncthreads();

    // ---- last block: fixed-order final reduction ----
    if (is_last) {
        int nb = gridDim.x;
        double s = 0.0;
        for (int b = tid; b < nb; b += TPB)
            s += (double)g_part[b];
        #pragma unroll
        for (int o = 16; o > 0; o >>= 1)
            s += __shfl_down_sync(0xffffffffu, s, o);
        __shared__ double dsum[4];
        if (lane == 0) dsum[wid] = s;
        __syncthreads();
        if (wid == 0) {
            double v = (lane < 4) ? dsum[lane] : 0.0;
            v += __shfl_down_sync(0xffffffffu, v, 2);
            v += __shfl_down_sync(0xffffffffu, v, 1);
            if (lane == 0) {
                out[0] = (float)(v * (double)inv_n);
                g_ticket = 0u;
            }
        }
    }
}

extern "C" void kernel_launch(void* const* d_in, const int* in_sizes, int n_in,
                              void* d_out, int out_size) {
    const float* pred   = (const float*)d_in[0];
    const float* target = (const float*)d_in[1];
    const float* wgt    = (const float*)d_in[2];
    float* out = (float*)d_out;

    int n = in_sizes[2];
    if (n * 5 != in_sizes[0]) n = in_sizes[0] / 5;

    int blocks = (n + TPB - 1) / TPB;   // 500k -> 3907 (< 8192)

    rotated_iou_loss_kernel<<<blocks, TPB>>>(pred, target, wgt, out,
                                             n, 1.0f / (float)n);
}

// round 11
// speedup vs baseline: 1.0610x; 1.0610x over previous
#include <cuda_runtime.h>
#include <math.h>

#define EPSF 1e-6f
#define TPB 128

__device__ float g_part[8192];
__device__ unsigned int g_ticket;   // zero-init; self-resets each launch

__global__ __launch_bounds__(TPB)
void rotated_iou_loss_kernel(const float* __restrict__ pred,
                             const float* __restrict__ target,
                             const float* __restrict__ weight,
                             float* __restrict__ out,
                             int n, float inv_n)
{
    // One pool, two lives: staging (10*TPB floats) then clip buffers
    // (float2 [slot][tid], 6 + 8 slots). Conflict-free in both lives.
    __shared__ __align__(16) char pool[14 * TPB * sizeof(float2)];
    float* sIn = (float*)pool;

    int tid = threadIdx.x;
    int i = blockIdx.x * TPB + tid;

    {   // coalesced staging
        int base = blockIdx.x * TPB * 5;
        int n5 = 5 * n;
        #pragma unroll
        for (int c = 0; c < 5; c++) {
            int k = tid + c * TPB;
            int g = base + k;
            bool ok = g < n5;
            sIn[k]           = ok ? pred[g]   : 0.0f;
            sIn[5 * TPB + k] = ok ? target[g] : 0.0f;
        }
    }
    __syncthreads();

    int r5 = tid * 5;   // stride-5 smem reads: gcd(5,32)=1 -> conflict-free
    float p_x = sIn[r5+0], p_y = sIn[r5+1], p_w = sIn[r5+2],
          p_h = sIn[r5+3], p_a = sIn[r5+4];
    float t_x = sIn[5*TPB+r5+0], t_y = sIn[5*TPB+r5+1], t_w = sIn[5*TPB+r5+2],
          t_h = sIn[5*TPB+r5+3], t_a = sIn[5*TPB+r5+4];
    __syncthreads();   // staging dead -> pool becomes clip buffers

    float2* pB = (float2*)pool + tid;              // x-slab output, <=6 slots
    float2* pC = (float2*)pool + 6 * TPB + tid;    // y-slab output, <=8 slots

    float loss = 0.0f;
    if (i < n) {
        float tc, ts, cd, sd;
        __sincosf(t_a, &ts, &tc);
        __sincosf(p_a - t_a, &sd, &cd);

        float rx = p_x - t_x, ry = p_y - t_y;
        float cu =  rx * tc + ry * ts;
        float cv = -rx * ts + ry * tc;

        // Pred quad (CCW, reference corner order) in target frame.
        const float dxs[4] = { 0.5f, -0.5f, -0.5f,  0.5f };
        const float dys[4] = { 0.5f,  0.5f, -0.5f, -0.5f };
        float qx[4], qy[4];
        #pragma unroll
        for (int j = 0; j < 4; j++) {
            float lx = p_w * dxs[j], ly = p_h * dys[j];
            qx[j] = cu + lx * cd - ly * sd;
            qy[j] = cv + lx * sd + ly * cd;
        }

        float hw = t_w * 0.5f, hh = t_h * 0.5f;

        // ---- Stage 1: x-slab |x| <= hw (registers -> pB) ----
        float2* curB = pB;
        #pragma unroll
        for (int j = 0; j < 4; j++) {
            float px = qx[j],         py = qy[j];
            float cx = qx[(j+1) & 3], cy = qy[(j+1) & 3];
            bool pL = px < -hw, pH = px > hw;
            bool cL = cx < -hw, cH = cx > hw;
            float dx = cx - px, dy = cy - py;
            float inv = __fdividef(1.0f, dx);
            bool crossL = (pL != cL), crossH = (pH != cH);
            bool firstIsL = dx > 0.0f;
            #pragma unroll
            for (int e = 0; e < 2; e++) {
                bool doL = (e == 0) ? firstIsL : !firstIsL;
                bool cr  = doL ? crossL : crossH;
                if (cr) {
                    float bnd = doL ? -hw : hw;
                    float t = (bnd - px) * inv;
                    *curB = make_float2(bnd, fmaf(t, dy, py));
                    curB += TPB;
                }
            }
            if (!cL && !cH) { *curB = make_float2(cx, cy); curB += TPB; }
        }
        int m1 = (int)((curB - pB) >> 7);   // /TPB  (0 <= m1 <= 6)

        // ---- Stage 2: y-slab |y| <= hh (pB -> pC), fused sums ----
        // FIXED 6 iterations (m1 <= 6): uniform control flow, immediate-offset
        // loads. Centroid cancels in cyclic shoelace -> accumulate S on raw
        // coords at emission.
        float sx = 0.0f, sy = 0.0f, S = 0.0f;
        float fex = 0.0f, fey = 0.0f, prx = 0.0f, pry = 0.0f;
        float2* curC = pC;

        #define EMIT(ex_, ey_) do {                                  \
            float _ex = (ex_), _ey = (ey_);                          \
            if (curC == pC) { fex = _ex; fey = _ey; }                \
            else            { S += prx * _ey - pry * _ex; }          \
            *curC = make_float2(_ex, _ey); curC += TPB;              \
            sx += _ex; sy += _ey;                                    \
            prx = _ex; pry = _ey;                                    \
        } while (0)

        {
            int lastB = (m1 > 0) ? (m1 - 1) : 0;
            float2 prev = pB[lastB * TPB];         // one dynamic LDS.64
            float px = prev.x, py = prev.y;
            bool pLo = py < -hh, pHi = py > hh;
            #pragma unroll
            for (int j = 0; j < 6; j++) {
                bool act = j < m1;
                float2 cur = pB[j * TPB];          // immediate-offset LDS.64
                float cx = cur.x, cy = cur.y;
                bool cLo = cy < -hh, cHi = cy > hh;
                float dx = cx - px, dy = cy - py;
                float inv = __fdividef(1.0f, dy);
                bool crossL = (pLo != cLo), crossH = (pHi != cHi);
                bool firstIsL = dy > 0.0f;
                #pragma unroll
                for (int e = 0; e < 2; e++) {
                    bool doL = (e == 0) ? firstIsL : !firstIsL;
                    bool cr  = act && (doL ? crossL : crossH);
                    if (cr) {
                        float bnd = doL ? -hh : hh;
                        float t = (bnd - py) * inv;
                        EMIT(fmaf(t, dx, px), bnd);
                    }
                }
                if (act && !cLo && !cHi) EMIT(cx, cy);
                if (act) { px = cx; py = cy; pLo = cLo; pHi = cHi; }
            }
        }
        #undef EMIT
        int m2 = (int)((curC - pC) >> 7);          // 0 <= m2 <= 8
        if (m2 > 0) S += prx * fey - pry * fex;    // close the cycle

        // ---- Quirky correction: drop the branch-cut edge ----
        // Reference drops cross(p_maxang, p_minang); for a convex CCW polygon
        // that's the unique cyclic pair whose centroid-relative ORIGINAL-frame
        // y flips >=0 -> <0. FIXED 8 iterations, immediate-offset loads.
        float inter = 0.0f;
        if (m2 >= 3) {
            float invc = __fdividef(1.0f, (float)m2);
            float mx = sx * invc, my = sy * invc;
            float wcy = mx * ts + my * tc;   // centroid's original-frame y

            float ax = mx, ay = my, bx = mx, by = my;  // default -> corr = 0
            float2 last = pC[(m2 - 1) * TPB];          // one dynamic LDS.64
            float ppx = last.x, ppy = last.y;
            float wyp = last.x * ts + last.y * tc;
            #pragma unroll
            for (int j = 0; j < 8; j++) {
                bool act = j < m2;
                float2 v = pC[j * TPB];                // immediate-offset
                float wy = v.x * ts + v.y * tc;
                if (act && wyp >= wcy && wy < wcy) {
                    ax = ppx; ay = ppy; bx = v.x; by = v.y;
                }
                if (act) { ppx = v.x; ppy = v.y; wyp = wy; }
            }

            float qax = ax - mx, qay = ay - my;
            float qbx = bx - mx, qby = by - my;
            float quirky = S - (qax * qby - qay * qbx);
            inter = 0.5f * fabsf(quirky);
        }

        float uni = p_w * p_h + t_w * t_h - inter;
        float iou = __fdividef(inter, fmaxf(uni, EPSF));
        iou = fmaxf(iou, EPSF);
        loss = (1.0f - iou * iou * iou) * weight[i];
    }

    // ---- block reduction -> per-block partial (deterministic) ----
    #pragma unroll
    for (int o = 16; o > 0; o >>= 1)
        loss += __shfl_down_sync(0xffffffffu, loss, o);

    __shared__ float warp_sums[4];
    __shared__ int is_last;
    int lane = tid & 31;
    int wid  = tid >> 5;
    if (lane == 0) warp_sums[wid] = loss;
    __syncthreads();

    if (wid == 0) {
        float v = (lane < 4) ? warp_sums[lane] : 0.0f;
        v += __shfl_down_sync(0xffffffffu, v, 2);
        v += __shfl_down_sync(0xffffffffu, v, 1);
        if (lane == 0) {
            g_part[blockIdx.x] = v;
            __threadfence();
            unsigned int t = atomicAdd(&g_ticket, 1u);
            is_last = (t == gridDim.x - 1) ? 1 : 0;
        }
    }
    __syncthreads();

    // ---- last block: fixed-order final reduction ----
    if (is_last) {
        int nb = gridDim.x;
        double s = 0.0;
        for (int b = tid; b < nb; b += TPB)
            s += (double)g_part[b];
        #pragma unroll
        for (int o = 16; o > 0; o >>= 1)
            s += __shfl_down_sync(0xffffffffu, s, o);
        __shared__ double dsum[4];
        if (lane == 0) dsum[wid] = s;
        __syncthreads();
        if (wid == 0) {
            double v = (lane < 4) ? dsum[lane] : 0.0;
            v += __shfl_down_sync(0xffffffffu, v, 2);
            v += __shfl_down_sync(0xffffffffu, v, 1);
            if (lane == 0) {
                out[0] = (float)(v * (double)inv_n);
                g_ticket = 0u;
            }
        }
    }
}

extern "C" void kernel_launch(void* const* d_in, const int* in_sizes, int n_in,
                              void* d_out, int out_size) {
    const float* pred   = (const float*)d_in[0];
    const float* target = (const float*)d_in[1];
    const float* wgt    = (const float*)d_in[2];
    float* out = (float*)d_out;

    int n = in_sizes[2];
    if (n * 5 != in_sizes[0]) n = in_sizes[0] / 5;

    int blocks = (n + TPB - 1) / TPB;   // 500k -> 3907 (< 8192)

    rotated_iou_loss_kernel<<<blocks, TPB>>>(pred, target, wgt, out,
                                             n, 1.0f / (float)n);
}